// round 2
// baseline (speedup 1.0000x reference)
#include <cuda_runtime.h>
#include <cuda_bf16.h>
#include <cstdint>
#include <math.h>

// ============================================================================
// CliffordLinear == GEMM  Out[65536,512] = X[65536,512] @ W2t[512,512]^T + bias
// Split-bf16 (hi/lo) mma.sync GEMM: xh@wh + xh@wl + xl@wh  (~fp32 accuracy)
// (tcgen05 is unavailable: harness compiles PTX with .target sm_103, not 103a)
// ============================================================================

#define KDIM     512
#define NDIM     512
#define M_TILE   128
#define N_TILE   128
#define K_CHUNK  64
#define NCHUNKS  8
#define THREADS  256

// per-buffer smem layout (bytes), each tile is 128 rows x 128B (SW128)
#define OFF_AH   0
#define OFF_AL   16384
#define OFF_BH   32768
#define OFF_BL   49152
#define BUFSZ    65536
#define SMEM_BYTES (2 * BUFSZ + 1024)

// ---------------- device scratch (no cudaMalloc allowed) -------------------
__device__ __nv_bfloat16 g_Wh[NDIM * KDIM];
__device__ __nv_bfloat16 g_Wl[NDIM * KDIM];
__device__ float         g_bias[NDIM];

// (i,k) -> unique j with C[i,j,k] != 0, and its sign
__constant__ int c_J[64] = {
  0,1,2,3,4,5,6,7,
  1,0,4,5,2,3,7,6,
  2,4,0,6,1,7,3,5,
  3,5,6,0,7,1,2,4,
  4,2,1,7,0,6,5,3,
  5,3,7,1,6,0,4,2,
  6,7,3,2,5,4,0,1,
  7,6,5,4,3,2,1,0 };
__constant__ float c_S[64] = {
   1, 1, 1, 1, 1, 1, 1, 1,
   1, 1, 1, 1, 1, 1, 1, 1,
   1,-1, 1, 1,-1,-1, 1,-1,
   1,-1,-1, 1, 1,-1,-1, 1,
  -1, 1,-1,-1, 1, 1,-1, 1,
  -1, 1, 1,-1,-1, 1, 1,-1,
  -1,-1, 1,-1, 1,-1, 1, 1,
  -1,-1, 1,-1, 1,-1, 1, 1 };

// ---------------- helpers ---------------------------------------------------
__device__ __forceinline__ uint32_t smem_u32(const void* p) {
    uint32_t a;
    asm("{ .reg .u64 t; cvta.to.shared.u64 t, %1; cvt.u32.u64 %0, t; }"
        : "=r"(a) : "l"(p));
    return a;
}
__device__ __forceinline__ uint32_t sw128(uint32_t off) {
    return off ^ ((off >> 3) & 0x70);
}
__device__ __forceinline__ uint32_t pack_bf16(__nv_bfloat16 a, __nv_bfloat16 b) {
    __nv_bfloat162 t(a, b);
    return *reinterpret_cast<uint32_t*>(&t);
}

#define LDSM4(r0, r1, r2, r3, addr)                                          \
    asm volatile("ldmatrix.sync.aligned.m8n8.x4.shared.b16 {%0,%1,%2,%3}, [%4];" \
        : "=r"(r0), "=r"(r1), "=r"(r2), "=r"(r3) : "r"(addr))

#define MMA_BF16(d, a, b)                                                    \
    asm volatile("mma.sync.aligned.m16n8k16.row.col.f32.bf16.bf16.f32 "      \
        "{%0,%1,%2,%3}, {%4,%5,%6,%7}, {%8,%9}, {%0,%1,%2,%3};"              \
        : "+f"((d)[0]), "+f"((d)[1]), "+f"((d)[2]), "+f"((d)[3])             \
        : "r"((a)[0]), "r"((a)[1]), "r"((a)[2]), "r"((a)[3]),                \
          "r"((b)[0]), "r"((b)[1]))

#define CP_ASYNC16(dst, src)                                                 \
    asm volatile("cp.async.cg.shared.global [%0], [%1], 16;"                 \
        :: "r"(dst), "l"(src) : "memory")
#define CP_COMMIT()  asm volatile("cp.async.commit_group;" ::: "memory")
#define CP_WAIT0()   asm volatile("cp.async.wait_group 0;" ::: "memory")

// ============================================================================
// Kernel 1: fold structure constants + scales into W2t, split into bf16 hi/lo
// ============================================================================
__global__ void precompute_kernel(const float* __restrict__ w,
                                  const float* __restrict__ bias,
                                  const float* __restrict__ rs,
                                  const float* __restrict__ cs,
                                  const float* __restrict__ bsh) {
    int idx = blockIdx.x * blockDim.x + threadIdx.x;   // 0 .. 512*512-1
    int oc = idx >> 9, ic = idx & 511;
    int o = oc >> 3, k = oc & 7, n = ic >> 3, i = ic & 7;
    int j   = c_J[i * 8 + k];
    float s = c_S[i * 8 + k];
    float val = w[(o * 64 + n) * 8 + j] * rs[o] * cs[n];
    if (isnan(val)) val = 0.0f;
    else if (isinf(val)) val = copysignf(3.4028234663852886e38f, val);
    val *= s;
    __nv_bfloat16 hi = __float2bfloat16_rn(val);
    float lo = val - __bfloat162float(hi);
    g_Wh[oc * KDIM + ic] = hi;
    g_Wl[oc * KDIM + ic] = __float2bfloat16_rn(lo);
    if (idx < NDIM) {
        float b = bias[idx];                 // bias is [64,8] contiguous == [oc]
        if ((idx & 7) == 0) b += bsh[idx >> 3];
        g_bias[idx] = b;
    }
}

// ============================================================================
// Kernel 2: split-bf16 mma.sync GEMM.  Per CTA: 128(M) x 128(N) x 512(K)
// ============================================================================
__global__ void __launch_bounds__(THREADS, 1)
clifford_gemm(const float* __restrict__ x, float* __restrict__ out) {
    extern __shared__ char smem_raw[];
    uint32_t base0 = smem_u32(smem_raw);
    uint32_t sb    = (base0 + 1023u) & ~1023u;   // 1024-aligned for SW128

    const int tid    = threadIdx.x;
    const int lane   = tid & 31;
    const int wid    = tid >> 5;
    const int warp_m = wid & 1;     // 2 warps along M  -> warp tile 64 rows
    const int warp_n = wid >> 1;    // 4 warps along N  -> warp tile 32 cols

    const int m0 = blockIdx.y * M_TILE;
    const int n0 = blockIdx.x * N_TILE;

    // A global-load mapping: 128 rows x 16 float4 per chunk, 256 threads
    const int a_q  = tid & 15;          // float4 index within row (0..15)
    const int a_r0 = tid >> 4;          // base row (stride 16, 8 passes)
    const float* xbase = x + (size_t)m0 * KDIM + a_q * 4;

    float acc[4][4][4];
    #pragma unroll
    for (int mi = 0; mi < 4; ++mi)
        #pragma unroll
        for (int ni = 0; ni < 4; ++ni)
            #pragma unroll
            for (int r = 0; r < 4; ++r) acc[mi][ni][r] = 0.0f;

    // ---------------- prologue: stage chunk 0 ------------------------------
    {
        #pragma unroll
        for (int j = 0; j < 8; ++j) {
            int row  = a_r0 + j * 16;
            float4 f = *reinterpret_cast<const float4*>(xbase + (size_t)row * KDIM);
            __nv_bfloat16 h0 = __float2bfloat16_rn(f.x);
            __nv_bfloat16 h1 = __float2bfloat16_rn(f.y);
            __nv_bfloat16 h2 = __float2bfloat16_rn(f.z);
            __nv_bfloat16 h3 = __float2bfloat16_rn(f.w);
            uint2 vh, vl;
            vh.x = pack_bf16(h0, h1); vh.y = pack_bf16(h2, h3);
            vl.x = pack_bf16(__float2bfloat16_rn(f.x - __bfloat162float(h0)),
                             __float2bfloat16_rn(f.y - __bfloat162float(h1)));
            vl.y = pack_bf16(__float2bfloat16_rn(f.z - __bfloat162float(h2)),
                             __float2bfloat16_rn(f.w - __bfloat162float(h3)));
            uint32_t sw = sw128((uint32_t)(row * 128 + a_q * 8));
            *reinterpret_cast<uint2*>((char*)0 + 0); // (no-op placeholder removed by compiler)
            asm volatile("st.shared.v2.b32 [%0], {%1,%2};" :: "r"(sb + OFF_AH + sw), "r"(vh.x), "r"(vh.y) : "memory");
            asm volatile("st.shared.v2.b32 [%0], {%1,%2};" :: "r"(sb + OFF_AL + sw), "r"(vl.x), "r"(vl.y) : "memory");
        }
        #pragma unroll
        for (int p = 0; p < 4; ++p) {
            int idx = tid + p * 256;
            int row = idx >> 3, q = idx & 7;
            uint32_t sw = sw128((uint32_t)(row * 128 + q * 16));
            const char* srch = (const char*)g_Wh + (size_t)(n0 + row) * 1024 + q * 16;
            const char* srcl = (const char*)g_Wl + (size_t)(n0 + row) * 1024 + q * 16;
            CP_ASYNC16(sb + OFF_BH + sw, srch);
            CP_ASYNC16(sb + OFF_BL + sw, srcl);
        }
        CP_COMMIT();
        CP_WAIT0();
        __syncthreads();
    }

    // ---------------- main loop over K chunks ------------------------------
    #pragma unroll 1
    for (int c = 0; c < NCHUNKS; ++c) {
        const uint32_t cur = sb + (uint32_t)(c & 1) * BUFSZ;
        float4 st[8];

        if (c < NCHUNKS - 1) {
            const int c0n = (c + 1) * K_CHUNK;
            #pragma unroll
            for (int j = 0; j < 8; ++j)
                st[j] = *reinterpret_cast<const float4*>(
                    xbase + (size_t)(a_r0 + j * 16) * KDIM + c0n);
            const uint32_t nxt = sb + (uint32_t)((c + 1) & 1) * BUFSZ;
            #pragma unroll
            for (int p = 0; p < 4; ++p) {
                int idx = tid + p * 256;
                int row = idx >> 3, q = idx & 7;
                uint32_t sw = sw128((uint32_t)(row * 128 + q * 16));
                const char* srch = (const char*)g_Wh + (size_t)(n0 + row) * 1024 + c0n * 2 + q * 16;
                const char* srcl = (const char*)g_Wl + (size_t)(n0 + row) * 1024 + c0n * 2 + q * 16;
                CP_ASYNC16(nxt + OFF_BH + sw, srch);
                CP_ASYNC16(nxt + OFF_BL + sw, srcl);
            }
            CP_COMMIT();
        }

        // -------- compute on current buffer: 4 k-steps of 16 ----------------
        #pragma unroll
        for (int ks = 0; ks < 4; ++ks) {
            uint32_t ah[4][4], al[4][4], bh[4][2], bl[4][2];
            #pragma unroll
            for (int mi = 0; mi < 4; ++mi) {
                uint32_t off = (uint32_t)((warp_m * 64 + mi * 16 + (lane & 15)) * 128
                                          + ks * 32 + (lane >> 4) * 16);
                uint32_t sw = sw128(off);
                LDSM4(ah[mi][0], ah[mi][1], ah[mi][2], ah[mi][3], cur + OFF_AH + sw);
                LDSM4(al[mi][0], al[mi][1], al[mi][2], al[mi][3], cur + OFF_AL + sw);
            }
            #pragma unroll
            for (int bt = 0; bt < 2; ++bt) {
                uint32_t off = (uint32_t)((warp_n * 32 + bt * 16 + (lane & 7) + ((lane >> 4) << 3)) * 128
                                          + ks * 32 + ((lane >> 3) & 1) * 16);
                uint32_t sw = sw128(off);
                uint32_t t0, t1, t2, t3;
                LDSM4(t0, t1, t2, t3, cur + OFF_BH + sw);
                bh[bt * 2][0] = t0; bh[bt * 2][1] = t1;
                bh[bt * 2 + 1][0] = t2; bh[bt * 2 + 1][1] = t3;
                LDSM4(t0, t1, t2, t3, cur + OFF_BL + sw);
                bl[bt * 2][0] = t0; bl[bt * 2][1] = t1;
                bl[bt * 2 + 1][0] = t2; bl[bt * 2 + 1][1] = t3;
            }
            #pragma unroll
            for (int mi = 0; mi < 4; ++mi)
                #pragma unroll
                for (int ni = 0; ni < 4; ++ni) {
                    MMA_BF16(acc[mi][ni], ah[mi], bh[ni]);
                    MMA_BF16(acc[mi][ni], ah[mi], bl[ni]);
                    MMA_BF16(acc[mi][ni], al[mi], bh[ni]);
                }
        }

        if (c < NCHUNKS - 1) {
            CP_WAIT0();   // next-chunk B resident before the barrier
            const uint32_t nxt = sb + (uint32_t)((c + 1) & 1) * BUFSZ;
            #pragma unroll
            for (int j = 0; j < 8; ++j) {
                int row = a_r0 + j * 16;
                float4 f = st[j];
                __nv_bfloat16 h0 = __float2bfloat16_rn(f.x);
                __nv_bfloat16 h1 = __float2bfloat16_rn(f.y);
                __nv_bfloat16 h2 = __float2bfloat16_rn(f.z);
                __nv_bfloat16 h3 = __float2bfloat16_rn(f.w);
                uint2 vh, vl;
                vh.x = pack_bf16(h0, h1); vh.y = pack_bf16(h2, h3);
                vl.x = pack_bf16(__float2bfloat16_rn(f.x - __bfloat162float(h0)),
                                 __float2bfloat16_rn(f.y - __bfloat162float(h1)));
                vl.y = pack_bf16(__float2bfloat16_rn(f.z - __bfloat162float(h2)),
                                 __float2bfloat16_rn(f.w - __bfloat162float(h3)));
                uint32_t sw = sw128((uint32_t)(row * 128 + a_q * 8));
                asm volatile("st.shared.v2.b32 [%0], {%1,%2};" :: "r"(nxt + OFF_AH + sw), "r"(vh.x), "r"(vh.y) : "memory");
                asm volatile("st.shared.v2.b32 [%0], {%1,%2};" :: "r"(nxt + OFF_AL + sw), "r"(vl.x), "r"(vl.y) : "memory");
            }
        }
        __syncthreads();
    }

    // ---------------- epilogue: bias + store --------------------------------
    #pragma unroll
    for (int mi = 0; mi < 4; ++mi) {
        int grow = m0 + warp_m * 64 + mi * 16 + (lane >> 2);
        float* orow0 = out + (size_t)grow * NDIM;
        float* orow1 = orow0 + (size_t)8 * NDIM;
        #pragma unroll
        for (int ni = 0; ni < 4; ++ni) {
            int gcol = n0 + warp_n * 32 + ni * 8 + 2 * (lane & 3);
            float2 b = *reinterpret_cast<const float2*>(&g_bias[gcol]);
            float2 v0, v1;
            v0.x = acc[mi][ni][0] + b.x;  v0.y = acc[mi][ni][1] + b.y;
            v1.x = acc[mi][ni][2] + b.x;  v1.y = acc[mi][ni][3] + b.y;
            *reinterpret_cast<float2*>(orow0 + gcol) = v0;
            *reinterpret_cast<float2*>(orow1 + gcol) = v1;
        }
    }
}

// ============================================================================
extern "C" void kernel_launch(void* const* d_in, const int* in_sizes, int n_in,
                              void* d_out, int out_size) {
    const float* x    = (const float*)d_in[0];
    const float* w    = (const float*)d_in[1];
    const float* bias = (const float*)d_in[2];
    const float* rs   = (const float*)d_in[3];
    const float* cs   = (const float*)d_in[4];
    const float* bsh  = (const float*)d_in[5];
    float* out = (float*)d_out;

    cudaFuncSetAttribute(clifford_gemm,
                         cudaFuncAttributeMaxDynamicSharedMemorySize, SMEM_BYTES);

    precompute_kernel<<<(NDIM * KDIM) / 256, 256>>>(w, bias, rs, cs, bsh);
    dim3 grid(NDIM / N_TILE, 65536 / M_TILE);   // N fastest -> x-tile L2 reuse
    clifford_gemm<<<grid, THREADS, SMEM_BYTES>>>(x, out);
}

// round 3
// speedup vs baseline: 1.5205x; 1.5205x over previous
#include <cuda_runtime.h>
#include <cuda_fp16.h>
#include <cstdint>
#include <math.h>

// ============================================================================
// CliffordLinear == GEMM  Out[65536,512] = X[65536,512] @ W2t[512,512]^T + bias
// fp16 2-term scheme:  out = x16 @ Wh + x16 @ Wl   (Wh+Wl = W to ~2^-22)
// x pre-converted to fp16 in a separate pass -> GEMM is pure cp.async + HMMA.
// ============================================================================

#define KDIM     512
#define NDIM     512
#define M_TILE   128
#define N_TILE   128
#define K_CHUNK  64
#define NCHUNKS  8
#define THREADS  256

// per-buffer smem layout (bytes): tiles are rows x 128B, SW128-swizzled
#define OFF_A    0
#define OFF_BH   16384
#define OFF_BL   32768
#define BUFSZ    49152
#define SMEM_BYTES (2 * BUFSZ + 1024)

// ---------------- device scratch (no cudaMalloc allowed) -------------------
__device__ __half g_Xh[65536 * KDIM];          // 64 MB fp16 copy of x
__device__ __half g_Wh[NDIM * KDIM];
__device__ __half g_Wl[NDIM * KDIM];
__device__ float  g_bias[NDIM];

// (i,k) -> unique j with C[i,j,k] != 0, and its sign
__constant__ int c_J[64] = {
  0,1,2,3,4,5,6,7,
  1,0,4,5,2,3,7,6,
  2,4,0,6,1,7,3,5,
  3,5,6,0,7,1,2,4,
  4,2,1,7,0,6,5,3,
  5,3,7,1,6,0,4,2,
  6,7,3,2,5,4,0,1,
  7,6,5,4,3,2,1,0 };
__constant__ float c_S[64] = {
   1, 1, 1, 1, 1, 1, 1, 1,
   1, 1, 1, 1, 1, 1, 1, 1,
   1,-1, 1, 1,-1,-1, 1,-1,
   1,-1,-1, 1, 1,-1,-1, 1,
  -1, 1,-1,-1, 1, 1,-1, 1,
  -1, 1, 1,-1,-1, 1, 1,-1,
  -1,-1, 1,-1, 1,-1, 1, 1,
  -1,-1, 1,-1, 1,-1, 1, 1 };

// ---------------- helpers ---------------------------------------------------
__device__ __forceinline__ uint32_t smem_u32(const void* p) {
    uint32_t a;
    asm("{ .reg .u64 t; cvta.to.shared.u64 t, %1; cvt.u32.u64 %0, t; }"
        : "=r"(a) : "l"(p));
    return a;
}
__device__ __forceinline__ uint32_t sw128(uint32_t off) {
    return off ^ ((off >> 3) & 0x70);
}

#define LDSM4(r0, r1, r2, r3, addr)                                          \
    asm volatile("ldmatrix.sync.aligned.m8n8.x4.shared.b16 {%0,%1,%2,%3}, [%4];" \
        : "=r"(r0), "=r"(r1), "=r"(r2), "=r"(r3) : "r"(addr))

#define MMA_F16(d, a, b)                                                     \
    asm volatile("mma.sync.aligned.m16n8k16.row.col.f32.f16.f16.f32 "        \
        "{%0,%1,%2,%3}, {%4,%5,%6,%7}, {%8,%9}, {%0,%1,%2,%3};"              \
        : "+f"((d)[0]), "+f"((d)[1]), "+f"((d)[2]), "+f"((d)[3])             \
        : "r"((a)[0]), "r"((a)[1]), "r"((a)[2]), "r"((a)[3]),                \
          "r"((b)[0]), "r"((b)[1]))

#define CP_ASYNC16(dst, src)                                                 \
    asm volatile("cp.async.cg.shared.global [%0], [%1], 16;"                 \
        :: "r"(dst), "l"(src) : "memory")
#define CP_COMMIT()  asm volatile("cp.async.commit_group;" ::: "memory")
#define CP_WAIT(n)   asm volatile("cp.async.wait_group %0;" :: "n"(n) : "memory")

// ============================================================================
// Kernel 1: fold structure constants + scales into W2t, split fp16 hi/lo
// ============================================================================
__global__ void precompute_kernel(const float* __restrict__ w,
                                  const float* __restrict__ bias,
                                  const float* __restrict__ rs,
                                  const float* __restrict__ cs,
                                  const float* __restrict__ bsh) {
    int idx = blockIdx.x * blockDim.x + threadIdx.x;   // 0 .. 512*512-1
    int oc = idx >> 9, ic = idx & 511;
    int o = oc >> 3, k = oc & 7, n = ic >> 3, i = ic & 7;
    int j   = c_J[i * 8 + k];
    float s = c_S[i * 8 + k];
    float val = w[(o * 64 + n) * 8 + j] * rs[o] * cs[n];
    if (isnan(val)) val = 0.0f;
    val *= s;
    // clamp to fp16-representable to avoid inf in half
    val = fminf(fmaxf(val, -65504.0f), 65504.0f);
    __half hi = __float2half_rn(val);
    float lo = val - __half2float(hi);
    g_Wh[oc * KDIM + ic] = hi;
    g_Wl[oc * KDIM + ic] = __float2half_rn(lo);
    if (idx < NDIM) {
        float b = bias[idx];                 // bias is [64,8] contiguous == [oc]
        if ((idx & 7) == 0) b += bsh[idx >> 3];
        g_bias[idx] = b;
    }
}

// ============================================================================
// Kernel 2: convert x (fp32) -> g_Xh (fp16), 8 floats per thread
// ============================================================================
__global__ void convert_x_kernel(const float4* __restrict__ x) {
    size_t i = (size_t)blockIdx.x * blockDim.x + threadIdx.x;  // handles 8 floats
    float4 a = x[2 * i];
    float4 b = x[2 * i + 1];
    __half2 h0 = __floats2half2_rn(a.x, a.y);
    __half2 h1 = __floats2half2_rn(a.z, a.w);
    __half2 h2 = __floats2half2_rn(b.x, b.y);
    __half2 h3 = __floats2half2_rn(b.z, b.w);
    uint4 v;
    v.x = *reinterpret_cast<uint32_t*>(&h0);
    v.y = *reinterpret_cast<uint32_t*>(&h1);
    v.z = *reinterpret_cast<uint32_t*>(&h2);
    v.w = *reinterpret_cast<uint32_t*>(&h3);
    reinterpret_cast<uint4*>(g_Xh)[i] = v;
}

// ============================================================================
// Kernel 3: fp16 2-term mma.sync GEMM.  Per CTA: 128(M) x 128(N) x 512(K)
// 2 CTAs/SM (regs forced <=128), all operands staged via cp.async.
// ============================================================================
__global__ void __launch_bounds__(THREADS, 2)
clifford_gemm(float* __restrict__ out) {
    extern __shared__ char smem_raw[];
    uint32_t base0 = smem_u32(smem_raw);
    uint32_t sb    = (base0 + 1023u) & ~1023u;   // 1024-aligned for SW128

    const int tid    = threadIdx.x;
    const int lane   = tid & 31;
    const int wid    = tid >> 5;
    const int warp_m = wid & 1;     // 2 warps along M  -> warp tile 64 rows
    const int warp_n = wid >> 1;    // 4 warps along N  -> warp tile 32 cols

    const int m0 = blockIdx.y * M_TILE;
    const int n0 = blockIdx.x * N_TILE;

    // staging maps: 1024 x 16B lines per tile, 4 lines per thread
    const int s_row = tid >> 3;     // base row (stride 32 over 4 passes)
    const int s_q   = tid & 7;      // 16B segment within 128B row

    const char* Abase = (const char*)g_Xh + (size_t)(m0 + s_row) * 1024 + s_q * 16;
    const char* Hbase = (const char*)g_Wh + (size_t)(n0 + s_row) * 1024 + s_q * 16;
    const char* Lbase = (const char*)g_Wl + (size_t)(n0 + s_row) * 1024 + s_q * 16;

    float acc[4][4][4];
    #pragma unroll
    for (int mi = 0; mi < 4; ++mi)
        #pragma unroll
        for (int ni = 0; ni < 4; ++ni)
            #pragma unroll
            for (int r = 0; r < 4; ++r) acc[mi][ni][r] = 0.0f;

    // ---- stage one K chunk (c0 = chunk * 64 columns = chunk*128 bytes) -----
    auto stage = [&](int c, uint32_t buf) {
        const size_t cb = (size_t)c * 128;   // byte offset along K
        #pragma unroll
        for (int p = 0; p < 4; ++p) {
            int row = s_row + p * 32;
            uint32_t sw = sw128((uint32_t)(row * 128 + s_q * 16));
            CP_ASYNC16(buf + OFF_A  + sw, Abase + (size_t)p * 32 * 1024 + cb);
            CP_ASYNC16(buf + OFF_BH + sw, Hbase + (size_t)p * 32 * 1024 + cb);
            CP_ASYNC16(buf + OFF_BL + sw, Lbase + (size_t)p * 32 * 1024 + cb);
        }
    };

    stage(0, sb);
    CP_COMMIT();

    #pragma unroll 1
    for (int c = 0; c < NCHUNKS; ++c) {
        const uint32_t cur = sb + (uint32_t)(c & 1) * BUFSZ;

        if (c < NCHUNKS - 1) {
            stage(c + 1, sb + (uint32_t)((c + 1) & 1) * BUFSZ);
            CP_COMMIT();
            CP_WAIT(1);            // chunk c resident (c+1 still in flight)
        } else {
            CP_WAIT(0);
        }
        __syncthreads();

        // -------- compute on current buffer: 4 k-steps of 16 ----------------
        #pragma unroll
        for (int ks = 0; ks < 4; ++ks) {
            uint32_t ah[4][4], bh[4][2], bl[4][2];
            #pragma unroll
            for (int mi = 0; mi < 4; ++mi) {
                uint32_t off = (uint32_t)((warp_m * 64 + mi * 16 + (lane & 15)) * 128
                                          + ks * 32 + (lane >> 4) * 16);
                LDSM4(ah[mi][0], ah[mi][1], ah[mi][2], ah[mi][3],
                      cur + OFF_A + sw128(off));
            }
            #pragma unroll
            for (int bt = 0; bt < 2; ++bt) {
                uint32_t off = (uint32_t)((warp_n * 32 + bt * 16 + (lane & 7) + ((lane >> 4) << 3)) * 128
                                          + ks * 32 + ((lane >> 3) & 1) * 16);
                uint32_t sw = sw128(off);
                uint32_t t0, t1, t2, t3;
                LDSM4(t0, t1, t2, t3, cur + OFF_BH + sw);
                bh[bt * 2][0] = t0; bh[bt * 2][1] = t1;
                bh[bt * 2 + 1][0] = t2; bh[bt * 2 + 1][1] = t3;
                LDSM4(t0, t1, t2, t3, cur + OFF_BL + sw);
                bl[bt * 2][0] = t0; bl[bt * 2][1] = t1;
                bl[bt * 2 + 1][0] = t2; bl[bt * 2 + 1][1] = t3;
            }
            #pragma unroll
            for (int mi = 0; mi < 4; ++mi)
                #pragma unroll
                for (int ni = 0; ni < 4; ++ni) {
                    MMA_F16(acc[mi][ni], ah[mi], bh[ni]);
                    MMA_F16(acc[mi][ni], ah[mi], bl[ni]);
                }
        }
        __syncthreads();   // compute done before this buffer is restaged
    }

    // ---------------- epilogue: bias + store --------------------------------
    #pragma unroll
    for (int mi = 0; mi < 4; ++mi) {
        int grow = m0 + warp_m * 64 + mi * 16 + (lane >> 2);
        float* orow0 = out + (size_t)grow * NDIM;
        float* orow1 = orow0 + (size_t)8 * NDIM;
        #pragma unroll
        for (int ni = 0; ni < 4; ++ni) {
            int gcol = n0 + warp_n * 32 + ni * 8 + 2 * (lane & 3);
            float2 b = *reinterpret_cast<const float2*>(&g_bias[gcol]);
            float2 v0, v1;
            v0.x = acc[mi][ni][0] + b.x;  v0.y = acc[mi][ni][1] + b.y;
            v1.x = acc[mi][ni][2] + b.x;  v1.y = acc[mi][ni][3] + b.y;
            *reinterpret_cast<float2*>(orow0 + gcol) = v0;
            *reinterpret_cast<float2*>(orow1 + gcol) = v1;
        }
    }
}

// ============================================================================
extern "C" void kernel_launch(void* const* d_in, const int* in_sizes, int n_in,
                              void* d_out, int out_size) {
    const float* x    = (const float*)d_in[0];
    const float* w    = (const float*)d_in[1];
    const float* bias = (const float*)d_in[2];
    const float* rs   = (const float*)d_in[3];
    const float* cs   = (const float*)d_in[4];
    const float* bsh  = (const float*)d_in[5];
    float* out = (float*)d_out;

    cudaFuncSetAttribute(clifford_gemm,
                         cudaFuncAttributeMaxDynamicSharedMemorySize, SMEM_BYTES);

    precompute_kernel<<<(NDIM * KDIM) / 256, 256>>>(w, bias, rs, cs, bsh);
    convert_x_kernel<<<(65536 * KDIM / 8) / 256, 256>>>((const float4*)x);
    dim3 grid(NDIM / N_TILE, 65536 / M_TILE);   // N fastest -> x-tile L2 reuse
    clifford_gemm<<<grid, THREADS, SMEM_BYTES>>>(out);
}

// round 4
// speedup vs baseline: 2.2555x; 1.4834x over previous
#include <cuda_runtime.h>
#include <cuda_fp16.h>
#include <cstdint>
#include <math.h>

// ============================================================================
// CliffordLinear == GEMM  Out[65536,512] = X[65536,512] @ W2t[512,512]^T + bias
// Single fp16 MMA scheme:  out = x16 @ W16   (rel_err ~1.3e-4 << 1e-3)
// x pre-converted to fp16; GEMM is pure cp.async(3-stage) + HMMA.
// ============================================================================

#define KDIM     512
#define NDIM     512
#define M_TILE   128
#define N_TILE   128
#define K_CHUNK  64
#define NCHUNKS  8
#define THREADS  256
#define STAGES   3

// per-stage smem layout (bytes): tiles are 128 rows x 128B, SW128-swizzled
#define OFF_A    0
#define OFF_B    16384
#define BUFSZ    32768
#define SMEM_BYTES (STAGES * BUFSZ + 1024)

// ---------------- device scratch (no cudaMalloc allowed) -------------------
__device__ __half g_Xh[65536 * KDIM];          // 64 MB fp16 copy of x
__device__ __half g_Wh[NDIM * KDIM];
__device__ float  g_bias[NDIM];

// (i,k) -> unique j with C[i,j,k] != 0, and its sign
__constant__ int c_J[64] = {
  0,1,2,3,4,5,6,7,
  1,0,4,5,2,3,7,6,
  2,4,0,6,1,7,3,5,
  3,5,6,0,7,1,2,4,
  4,2,1,7,0,6,5,3,
  5,3,7,1,6,0,4,2,
  6,7,3,2,5,4,0,1,
  7,6,5,4,3,2,1,0 };
__constant__ float c_S[64] = {
   1, 1, 1, 1, 1, 1, 1, 1,
   1, 1, 1, 1, 1, 1, 1, 1,
   1,-1, 1, 1,-1,-1, 1,-1,
   1,-1,-1, 1, 1,-1,-1, 1,
  -1, 1,-1,-1, 1, 1,-1, 1,
  -1, 1, 1,-1,-1, 1, 1,-1,
  -1,-1, 1,-1, 1,-1, 1, 1,
  -1,-1, 1,-1, 1,-1, 1, 1 };

// ---------------- helpers ---------------------------------------------------
__device__ __forceinline__ uint32_t smem_u32(const void* p) {
    uint32_t a;
    asm("{ .reg .u64 t; cvta.to.shared.u64 t, %1; cvt.u32.u64 %0, t; }"
        : "=r"(a) : "l"(p));
    return a;
}
__device__ __forceinline__ uint32_t sw128(uint32_t off) {
    return off ^ ((off >> 3) & 0x70);
}

#define LDSM4(r0, r1, r2, r3, addr)                                          \
    asm volatile("ldmatrix.sync.aligned.m8n8.x4.shared.b16 {%0,%1,%2,%3}, [%4];" \
        : "=r"(r0), "=r"(r1), "=r"(r2), "=r"(r3) : "r"(addr))

#define MMA_F16(d, a, b)                                                     \
    asm volatile("mma.sync.aligned.m16n8k16.row.col.f32.f16.f16.f32 "        \
        "{%0,%1,%2,%3}, {%4,%5,%6,%7}, {%8,%9}, {%0,%1,%2,%3};"              \
        : "+f"((d)[0]), "+f"((d)[1]), "+f"((d)[2]), "+f"((d)[3])             \
        : "r"((a)[0]), "r"((a)[1]), "r"((a)[2]), "r"((a)[3]),                \
          "r"((b)[0]), "r"((b)[1]))

#define CP_ASYNC16(dst, src)                                                 \
    asm volatile("cp.async.cg.shared.global [%0], [%1], 16;"                 \
        :: "r"(dst), "l"(src) : "memory")
#define CP_COMMIT()  asm volatile("cp.async.commit_group;" ::: "memory")
#define CP_WAIT(n)   asm volatile("cp.async.wait_group %0;" :: "n"(n) : "memory")

// ============================================================================
// Kernel 1: fold structure constants + scales into W2t (fp16)
// ============================================================================
__global__ void precompute_kernel(const float* __restrict__ w,
                                  const float* __restrict__ bias,
                                  const float* __restrict__ rs,
                                  const float* __restrict__ cs,
                                  const float* __restrict__ bsh) {
    int idx = blockIdx.x * blockDim.x + threadIdx.x;   // 0 .. 512*512-1
    int oc = idx >> 9, ic = idx & 511;
    int o = oc >> 3, k = oc & 7, n = ic >> 3, i = ic & 7;
    int j   = c_J[i * 8 + k];
    float s = c_S[i * 8 + k];
    float val = w[(o * 64 + n) * 8 + j] * rs[o] * cs[n];
    if (isnan(val)) val = 0.0f;
    val *= s;
    val = fminf(fmaxf(val, -65504.0f), 65504.0f);   // keep fp16-finite
    g_Wh[oc * KDIM + ic] = __float2half_rn(val);
    if (idx < NDIM) {
        float b = bias[idx];                 // bias is [64,8] contiguous == [oc]
        if ((idx & 7) == 0) b += bsh[idx >> 3];
        g_bias[idx] = b;
    }
}

// ============================================================================
// Kernel 2: convert x (fp32) -> g_Xh (fp16), 8 floats per thread
// ============================================================================
__global__ void convert_x_kernel(const float4* __restrict__ x) {
    size_t i = (size_t)blockIdx.x * blockDim.x + threadIdx.x;  // handles 8 floats
    float4 a = x[2 * i];
    float4 b = x[2 * i + 1];
    __half2 h0 = __floats2half2_rn(a.x, a.y);
    __half2 h1 = __floats2half2_rn(a.z, a.w);
    __half2 h2 = __floats2half2_rn(b.x, b.y);
    __half2 h3 = __floats2half2_rn(b.z, b.w);
    uint4 v;
    v.x = *reinterpret_cast<uint32_t*>(&h0);
    v.y = *reinterpret_cast<uint32_t*>(&h1);
    v.z = *reinterpret_cast<uint32_t*>(&h2);
    v.w = *reinterpret_cast<uint32_t*>(&h3);
    reinterpret_cast<uint4*>(g_Xh)[i] = v;
}

// ============================================================================
// Kernel 3: fp16 mma.sync GEMM.  Per CTA: 128(M) x 128(N) x 512(K)
// 2 CTAs/SM, 3-stage cp.async pipeline.
// ============================================================================
__global__ void __launch_bounds__(THREADS, 2)
clifford_gemm(float* __restrict__ out) {
    extern __shared__ char smem_raw[];
    uint32_t base0 = smem_u32(smem_raw);
    uint32_t sb    = (base0 + 1023u) & ~1023u;   // 1024-aligned for SW128

    const int tid    = threadIdx.x;
    const int lane   = tid & 31;
    const int wid    = tid >> 5;
    const int warp_m = wid & 1;     // 2 warps along M  -> warp tile 64 rows
    const int warp_n = wid >> 1;    // 4 warps along N  -> warp tile 32 cols

    const int m0 = blockIdx.y * M_TILE;
    const int n0 = blockIdx.x * N_TILE;

    // staging maps: 1024 x 16B lines per tile, 4 lines per thread per tile
    const int s_row = tid >> 3;     // base row (stride 32 over 4 passes)
    const int s_q   = tid & 7;      // 16B segment within 128B row

    const char* Abase = (const char*)g_Xh + (size_t)(m0 + s_row) * 1024 + s_q * 16;
    const char* Bbase = (const char*)g_Wh + (size_t)(n0 + s_row) * 1024 + s_q * 16;

    float acc[4][4][4];
    #pragma unroll
    for (int mi = 0; mi < 4; ++mi)
        #pragma unroll
        for (int ni = 0; ni < 4; ++ni)
            #pragma unroll
            for (int r = 0; r < 4; ++r) acc[mi][ni][r] = 0.0f;

    auto stage = [&](int c) {
        const uint32_t buf = sb + (uint32_t)(c % STAGES) * BUFSZ;
        const size_t cb = (size_t)c * 128;   // byte offset along K
        #pragma unroll
        for (int p = 0; p < 4; ++p) {
            int row = s_row + p * 32;
            uint32_t sw = sw128((uint32_t)(row * 128 + s_q * 16));
            CP_ASYNC16(buf + OFF_A + sw, Abase + (size_t)p * 32 * 1024 + cb);
            CP_ASYNC16(buf + OFF_B + sw, Bbase + (size_t)p * 32 * 1024 + cb);
        }
        CP_COMMIT();
    };

    stage(0);
    stage(1);

    #pragma unroll 1
    for (int c = 0; c < NCHUNKS; ++c) {
        const uint32_t cur = sb + (uint32_t)(c % STAGES) * BUFSZ;

        if (c + 2 < NCHUNKS) {
            stage(c + 2);           // reuses buffer consumed at iter c-1
            CP_WAIT(2);             // chunk c resident, c+1/c+2 in flight
        } else if (c + 2 == NCHUNKS) {
            CP_WAIT(1);
        } else {
            CP_WAIT(0);
        }
        __syncthreads();

        // -------- compute on current buffer: 4 k-steps of 16 ----------------
        #pragma unroll
        for (int ks = 0; ks < 4; ++ks) {
            uint32_t ah[4][4], bh[4][2];
            #pragma unroll
            for (int mi = 0; mi < 4; ++mi) {
                uint32_t off = (uint32_t)((warp_m * 64 + mi * 16 + (lane & 15)) * 128
                                          + ks * 32 + (lane >> 4) * 16);
                LDSM4(ah[mi][0], ah[mi][1], ah[mi][2], ah[mi][3],
                      cur + OFF_A + sw128(off));
            }
            #pragma unroll
            for (int bt = 0; bt < 2; ++bt) {
                uint32_t off = (uint32_t)((warp_n * 32 + bt * 16 + (lane & 7) + ((lane >> 4) << 3)) * 128
                                          + ks * 32 + ((lane >> 3) & 1) * 16);
                uint32_t t0, t1, t2, t3;
                LDSM4(t0, t1, t2, t3, cur + OFF_B + sw128(off));
                bh[bt * 2][0] = t0; bh[bt * 2][1] = t1;
                bh[bt * 2 + 1][0] = t2; bh[bt * 2 + 1][1] = t3;
            }
            #pragma unroll
            for (int mi = 0; mi < 4; ++mi)
                #pragma unroll
                for (int ni = 0; ni < 4; ++ni)
                    MMA_F16(acc[mi][ni], ah[mi], bh[ni]);
        }
        __syncthreads();   // all warps done with cur before it's restaged
    }

    // ---------------- epilogue: bias + store --------------------------------
    #pragma unroll
    for (int mi = 0; mi < 4; ++mi) {
        int grow = m0 + warp_m * 64 + mi * 16 + (lane >> 2);
        float* orow0 = out + (size_t)grow * NDIM;
        float* orow1 = orow0 + (size_t)8 * NDIM;
        #pragma unroll
        for (int ni = 0; ni < 4; ++ni) {
            int gcol = n0 + warp_n * 32 + ni * 8 + 2 * (lane & 3);
            float2 b = *reinterpret_cast<const float2*>(&g_bias[gcol]);
            float2 v0, v1;
            v0.x = acc[mi][ni][0] + b.x;  v0.y = acc[mi][ni][1] + b.y;
            v1.x = acc[mi][ni][2] + b.x;  v1.y = acc[mi][ni][3] + b.y;
            *reinterpret_cast<float2*>(orow0 + gcol) = v0;
            *reinterpret_cast<float2*>(orow1 + gcol) = v1;
        }
    }
}

// ============================================================================
extern "C" void kernel_launch(void* const* d_in, const int* in_sizes, int n_in,
                              void* d_out, int out_size) {
    const float* x    = (const float*)d_in[0];
    const float* w    = (const float*)d_in[1];
    const float* bias = (const float*)d_in[2];
    const float* rs   = (const float*)d_in[3];
    const float* cs   = (const float*)d_in[4];
    const float* bsh  = (const float*)d_in[5];
    float* out = (float*)d_out;

    cudaFuncSetAttribute(clifford_gemm,
                         cudaFuncAttributeMaxDynamicSharedMemorySize, SMEM_BYTES);

    precompute_kernel<<<(NDIM * KDIM) / 256, 256>>>(w, bias, rs, cs, bsh);
    convert_x_kernel<<<(65536 * KDIM / 8) / 256, 256>>>((const float4*)x);
    dim3 grid(NDIM / N_TILE, 65536 / M_TILE);   // N fastest -> x-tile L2 reuse
    clifford_gemm<<<grid, THREADS, SMEM_BYTES>>>(out);
}